// round 4
// baseline (speedup 1.0000x reference)
#include <cuda_runtime.h>
#include <cuda_bf16.h>
#include <cstdint>

#define NN 65536
#define KK 8192
#define DD 256
#define BMM 256
#define TB 64
#define NT (KK/TB)
#define MARGIN 1.5e-3f
#define CAP 8

// smem byte offsets
#define SM_A     0          // 256 rows x 512B bf16 (swizzled)       131072
#define SM_E0    131072     // 64 x 512B                              32768
#define SM_E1    163840     //                                        32768
#define SM_CAND  196608     // u16[256][4][CAP]                       16384
#define SM_CNT   212992     // u8[256][4]                              1024
#define SM_OVFN  214016
#define SM_OVFR  214020     // int[256]
#define SM_PACK  215048     // 8B aligned
#define SMEM_BYTES 215056

__device__ float g_z2[NN];
__device__ float g_e2[KK];
__device__ int   g_idx[NN];
__device__ __nv_bfloat16 g_zbf[(size_t)NN * DD];
__device__ __nv_bfloat16 g_ebf[(size_t)KK * DD];

// ---------------- portable PTX helpers ----------------
__device__ __forceinline__ uint32_t smem_u32(const void* p) {
    uint32_t a;
    asm("{ .reg .u64 t; cvta.to.shared.u64 t, %1; cvt.u32.u64 %0, t; }" : "=r"(a) : "l"(p));
    return a;
}
__device__ __forceinline__ void ldsm4(uint32_t* r, uint32_t addr) {
    asm volatile("ldmatrix.sync.aligned.m8n8.x4.shared.b16 {%0,%1,%2,%3}, [%4];"
                 : "=r"(r[0]), "=r"(r[1]), "=r"(r[2]), "=r"(r[3]) : "r"(addr));
}
__device__ __forceinline__ void mma16816(float* c, const uint32_t* a, uint32_t b0, uint32_t b1) {
    asm volatile("mma.sync.aligned.m16n8k16.row.col.f32.bf16.bf16.f32 "
                 "{%0,%1,%2,%3}, {%4,%5,%6,%7}, {%8,%9}, {%0,%1,%2,%3};"
                 : "+f"(c[0]), "+f"(c[1]), "+f"(c[2]), "+f"(c[3])
                 : "r"(a[0]), "r"(a[1]), "r"(a[2]), "r"(a[3]), "r"(b0), "r"(b1));
}
__device__ __forceinline__ void cp16(uint32_t dst, const void* src) {
    asm volatile("cp.async.cg.shared.global [%0], [%1], 16;" :: "r"(dst), "l"(src) : "memory");
}
#define CP_COMMIT() asm volatile("cp.async.commit_group;" ::: "memory")
#define CP_WAIT(n)  asm volatile("cp.async.wait_group %0;" :: "n"(n) : "memory")

// ---------------- prep kernels ----------------
__global__ void to_bf16_kernel(const float* __restrict__ src, int which) {
    size_t i = (size_t)blockIdx.x * blockDim.x + threadIdx.x;   // float4 index
    float4 v = ((const float4*)src)[i];
    __nv_bfloat162* d2 = which ? (__nv_bfloat162*)g_ebf : (__nv_bfloat162*)g_zbf;
    d2[i * 2]     = __floats2bfloat162_rn(v.x, v.y);
    d2[i * 2 + 1] = __floats2bfloat162_rn(v.z, v.w);
}

__global__ void row_norm_kernel(const float* __restrict__ x, int which) {
    int row  = blockIdx.x * 8 + (threadIdx.x >> 5);
    int lane = threadIdx.x & 31;
    const float* p = x + (size_t)row * DD;
    double s = 0.0;
    #pragma unroll
    for (int i = 0; i < DD / 32; ++i) {
        float v = p[lane + i * 32];
        float q = v * v;
        s += (double)q;
    }
    #pragma unroll
    for (int o = 16; o; o >>= 1) s += __shfl_xor_sync(0xffffffffu, s, o);
    if (lane == 0) { if (which) g_e2[row] = (float)s; else g_z2[row] = (float)s; }
}

// ---------------- main: bf16 mma.sync screen + exact rescore ----------------
__global__ void __launch_bounds__(128, 1)
vq_mma_kernel(const float* __restrict__ zf, const float* __restrict__ ef) {
    extern __shared__ char smem[];
    uint32_t sb = smem_u32(smem);
    int tid = threadIdx.x, wid = tid >> 5, lid = tid & 31;

    if (tid == 0) *(int*)(smem + SM_OVFN) = 0;

    // ---- prologue cp.async: z tile + e tile0 (group0), e tile1 (group1) ----
    {
        int c16 = tid & 31;
        const char* zs = (const char*)g_zbf + (size_t)blockIdx.x * BMM * 512;
        #pragma unroll
        for (int i = 0; i < 64; ++i) {
            int r = i * 4 + wid;
            cp16(sb + SM_A + r * 512 + ((c16 ^ (r & 7)) << 4),
                 zs + (size_t)r * 512 + c16 * 16);
        }
        const char* es = (const char*)g_ebf;
        #pragma unroll
        for (int i = 0; i < 16; ++i) {
            int r = i * 4 + wid;
            cp16(sb + SM_E0 + r * 512 + ((c16 ^ (r & 7)) << 4),
                 es + (size_t)r * 512 + c16 * 16);
        }
        CP_COMMIT();
        #pragma unroll
        for (int i = 0; i < 16; ++i) {
            int r = i * 4 + wid;
            cp16(sb + SM_E1 + r * 512 + ((c16 ^ (r & 7)) << 4),
                 es + (size_t)(64 + r) * 512 + c16 * 16);
        }
        CP_COMMIT();
    }

    // per-lane ldmatrix geometry
    int lrow  = lid & 15;
    int khalf = lid >> 4;
    int sx    = lrow & 7;
    uint32_t aab[4], bboff[4];
    #pragma unroll
    for (int mt = 0; mt < 4; ++mt) aab[mt] = sb + SM_A + (wid * 64 + mt * 16 + lrow) * 512;
    #pragma unroll
    for (int np = 0; np < 4; ++np) bboff[np] = (np * 16 + lrow) * 512;

    int q = lid & 3, r0 = lid >> 2;
    float runmin[4][2];
    int   cnt[4][2];
    #pragma unroll
    for (int mt = 0; mt < 4; ++mt)
        #pragma unroll
        for (int h = 0; h < 2; ++h) { runmin[mt][h] = __int_as_float(0x7f800000); cnt[mt][h] = 0; }

    uint16_t* candA = (uint16_t*)(smem + SM_CAND);
    const float2* e2f2 = (const float2*)g_e2;

    for (int t = 0; t < NT; ++t) {
        if (t < NT - 1) { CP_WAIT(1); } else { CP_WAIT(0); }
        __syncthreads();

        float acc[4][8][4];
        #pragma unroll
        for (int mt = 0; mt < 4; ++mt)
            #pragma unroll
            for (int nt = 0; nt < 8; ++nt)
                #pragma unroll
                for (int e = 0; e < 4; ++e) acc[mt][nt][e] = 0.0f;

        uint32_t eb = sb + ((t & 1) ? SM_E1 : SM_E0);

        #pragma unroll 4
        for (int ks = 0; ks < 16; ++ks) {
            uint32_t swz = (uint32_t)((2 * ks + khalf) ^ sx) << 4;
            uint32_t br[4][4];
            #pragma unroll
            for (int np = 0; np < 4; ++np) ldsm4(br[np], eb + bboff[np] + swz);
            #pragma unroll
            for (int mt = 0; mt < 4; ++mt) {
                uint32_t ar[4];
                ldsm4(ar, aab[mt] + swz);
                #pragma unroll
                for (int np = 0; np < 4; ++np) {
                    mma16816(acc[mt][2 * np],     ar, br[np][0], br[np][2]);
                    mma16816(acc[mt][2 * np + 1], ar, br[np][1], br[np][3]);
                }
            }
        }
        __syncthreads();

        // issue tile t+2 into the buffer just freed
        if (t + 2 < NT) {
            int c16 = tid & 31;
            const char* es = (const char*)g_ebf + (size_t)(t + 2) * TB * 512;
            #pragma unroll
            for (int i = 0; i < 16; ++i) {
                int r = i * 4 + wid;
                cp16(eb + r * 512 + ((c16 ^ (r & 7)) << 4),
                     es + (size_t)r * 512 + c16 * 16);
            }
            CP_COMMIT();
        }

        // tile 0: min-only pre-pass so thresholds are finite
        if (t == 0) {
            #pragma unroll
            for (int nt = 0; nt < 8; ++nt) {
                float2 e2v = e2f2[t * 32 + q + nt * 4];
                #pragma unroll
                for (int mt = 0; mt < 4; ++mt)
                    #pragma unroll
                    for (int e = 0; e < 4; ++e) {
                        float s = fmaf(-2.0f, acc[mt][nt][e], (e & 1) ? e2v.y : e2v.x);
                        runmin[mt][e >> 1] = fminf(runmin[mt][e >> 1], s);
                    }
            }
            #pragma unroll
            for (int mt = 0; mt < 4; ++mt)
                #pragma unroll
                for (int h = 0; h < 2; ++h) {
                    float v = runmin[mt][h];
                    v = fminf(v, __shfl_xor_sync(0xffffffffu, v, 1));
                    v = fminf(v, __shfl_xor_sync(0xffffffffu, v, 2));
                    runmin[mt][h] = v;
                }
        }

        float thr[4][2];
        #pragma unroll
        for (int mt = 0; mt < 4; ++mt)
            #pragma unroll
            for (int h = 0; h < 2; ++h) thr[mt][h] = runmin[mt][h] + MARGIN;

        #pragma unroll
        for (int nt = 0; nt < 8; ++nt) {
            float2 e2v = e2f2[t * 32 + q + nt * 4];
            #pragma unroll
            for (int mt = 0; mt < 4; ++mt) {
                #pragma unroll
                for (int e = 0; e < 4; ++e) {
                    int h = e >> 1;
                    float s = fmaf(-2.0f, acc[mt][nt][e], (e & 1) ? e2v.y : e2v.x);
                    if (s <= thr[mt][h]) {
                        int row = wid * 64 + mt * 16 + r0 + h * 8;
                        if (cnt[mt][h] < CAP)
                            candA[(row * 4 + q) * CAP + cnt[mt][h]] =
                                (uint16_t)(t * TB + nt * 8 + q * 2 + (e & 1));
                        cnt[mt][h]++;
                    }
                    runmin[mt][h] = fminf(runmin[mt][h], s);
                }
            }
        }
        #pragma unroll
        for (int mt = 0; mt < 4; ++mt)
            #pragma unroll
            for (int h = 0; h < 2; ++h) {
                float v = runmin[mt][h];
                v = fminf(v, __shfl_xor_sync(0xffffffffu, v, 1));
                v = fminf(v, __shfl_xor_sync(0xffffffffu, v, 2));
                runmin[mt][h] = v;
            }
    }

    // publish counts
    #pragma unroll
    for (int mt = 0; mt < 4; ++mt)
        #pragma unroll
        for (int h = 0; h < 2; ++h) {
            int row = wid * 64 + mt * 16 + r0 + h * 8;
            int c = cnt[mt][h];
            ((uint8_t*)(smem + SM_CNT))[row * 4 + q] = (uint8_t)(c > CAP ? CAP + 1 : c);
        }
    __syncthreads();

    // ---- exact fp32 rescore (verbatim R2 arithmetic) ----
    for (int rr = tid; rr < BMM; rr += 128) {
        int rowG = blockIdx.x * BMM + rr;
        const uint8_t* cp = (const uint8_t*)(smem + SM_CNT) + rr * 4;
        int c0 = cp[0], c1 = cp[1], c2 = cp[2], c3 = cp[3];
        if (c0 > CAP || c1 > CAP || c2 > CAP || c3 > CAP) {
            int s = atomicAdd((int*)(smem + SM_OVFN), 1);
            ((int*)(smem + SM_OVFR))[s] = rr;
            continue;
        }
        const float* zr = zf + (size_t)rowG * DD;
        float z2 = g_z2[rowG];
        uint32_t bestBits = 0xffffffffu; int bestK = 0;
        int cq[4] = {c0, c1, c2, c3};
        for (int qq = 0; qq < 4; ++qq) {
            for (int i = 0; i < cq[qq]; ++i) {
                int k = candA[(rr * 4 + qq) * CAP + i];
                const float* er = ef + (size_t)k * DD;
                float dot = 0.0f;
                #pragma unroll 4
                for (int d4 = 0; d4 < DD / 4; ++d4) {
                    float4 zv = ((const float4*)zr)[d4];
                    float4 ev = ((const float4*)er)[d4];
                    dot = fmaf(zv.x, ev.x, dot);
                    dot = fmaf(zv.y, ev.y, dot);
                    dot = fmaf(zv.z, ev.z, dot);
                    dot = fmaf(zv.w, ev.w, dot);
                }
                float t1 = z2 + g_e2[k];
                float dist = t1 - 2.0f * dot;
                uint32_t bits = __float_as_uint(dist);
                if (bits < bestBits || (bits == bestBits && k < bestK)) { bestBits = bits; bestK = k; }
            }
        }
        g_idx[rowG] = bestK;
    }
    __syncthreads();

    // ---- rare overflow fallback: cooperative exact full-row scan ----
    int novf = *(int*)(smem + SM_OVFN);
    unsigned long long* pack = (unsigned long long*)(smem + SM_PACK);
    for (int o = 0; o < novf; ++o) {
        int rr = ((int*)(smem + SM_OVFR))[o];
        int rG = blockIdx.x * BMM + rr;
        if (tid == 0) *pack = 0xffffffffffffffffULL;
        __syncthreads();
        const float* zr = zf + (size_t)rG * DD;
        float z2 = g_z2[rG];
        for (int k = tid; k < KK; k += 128) {
            const float* er = ef + (size_t)k * DD;
            float dot = 0.0f;
            #pragma unroll 4
            for (int d4 = 0; d4 < DD / 4; ++d4) {
                float4 zv = ((const float4*)zr)[d4];
                float4 ev = ((const float4*)er)[d4];
                dot = fmaf(zv.x, ev.x, dot);
                dot = fmaf(zv.y, ev.y, dot);
                dot = fmaf(zv.z, ev.z, dot);
                dot = fmaf(zv.w, ev.w, dot);
            }
            float t1 = z2 + g_e2[k];
            float dist = t1 - 2.0f * dot;
            unsigned long long p = ((unsigned long long)__float_as_uint(dist) << 32) | (unsigned)k;
            atomicMin(pack, p);
        }
        __syncthreads();
        if (tid == 0) g_idx[rG] = (int)(*pack & 0xffffffffu);
        __syncthreads();
    }
}

// ---------------- gather + writeout ----------------
__global__ void writeout_kernel(const float* __restrict__ e, float* __restrict__ out,
                                long long q_off, long long st_off, long long idx_off) {
    int row  = blockIdx.x * 8 + (threadIdx.x >> 5);
    int lane = threadIdx.x & 31;
    int idx  = g_idx[row];
    const float4* src = (const float4*)(e + (size_t)idx * DD);
    #pragma unroll
    for (int i = 0; i < 2; ++i) {
        float4 v = src[lane + i * 32];
        if (q_off >= 0)  ((float4*)(out + q_off))[(size_t)row * 64 + lane + i * 32] = v;
        if (st_off >= 0) ((float4*)(out + st_off))[(size_t)row * 64 + lane + i * 32] = v;
    }
    if (idx_off >= 0 && lane == 0) out[idx_off + row] = (float)idx;
}

extern "C" void kernel_launch(void* const* d_in, const int* in_sizes, int n_in,
                              void* d_out, int out_size) {
    const float* z = (const float*)d_in[0];
    const float* e = (const float*)d_in[1];
    float* out = (float*)d_out;

    cudaFuncSetAttribute(vq_mma_kernel,
                         cudaFuncAttributeMaxDynamicSharedMemorySize, SMEM_BYTES);

    to_bf16_kernel<<<(NN * DD / 4) / 256, 256>>>(z, 0);
    to_bf16_kernel<<<(KK * DD / 4) / 256, 256>>>(e, 1);
    row_norm_kernel<<<NN / 8, 256>>>(z, 0);
    row_norm_kernel<<<KK / 8, 256>>>(e, 1);

    vq_mma_kernel<<<NN / BMM, 128, SMEM_BYTES>>>(z, e);

    long long sz = out_size, pos = 0;
    long long q_off = -1, st_off = -1, idx_off = -1;
    if (sz - pos >= (long long)NN * DD) { q_off = pos;  pos += (long long)NN * DD; }
    if (sz - pos >= (long long)NN * DD) { st_off = pos; pos += (long long)NN * DD; }
    if (sz - pos >= NN)                 { idx_off = pos; }
    writeout_kernel<<<NN / 8, 256>>>(e, out, q_off, st_off, idx_off);
}

// round 5
// speedup vs baseline: 1.0275x; 1.0275x over previous
#include <cuda_runtime.h>
#include <cuda_fp16.h>
#include <cstdint>

#define NN 65536
#define KK 8192
#define DD 256
#define ND2 (DD/2)
#define BM 128
#define BN 256
#define NTT (KK/BN)      // 32 n-tiles
#define NCH 16           // 16 chunks of 8 d2 (16 d)
#define MARGIN 2.0e-3f
#define CAP 4

// smem byte offsets
#define SM_A     0          // u32[128 d2][128 m]            65536
#define SM_B     65536      // u32[2][8 d2][256 n]           16384
#define SM_CAND  81920      // u16[128 m][16 tx][CAP]        16384
#define SM_CNT   98304      // u8[128][16]                    2048
#define SM_OVFN  100352
#define SM_OVFR  100356     // int[128]
#define SM_PACK  100872     // 8B aligned
#define SMEM_BYTES 100880

__device__ float g_z2[NN];
__device__ float g_e2[KK];
__device__ int   g_idx[NN];
__device__ __half g_zh[(size_t)NN * DD];
__device__ __half g_eh[(size_t)KK * DD];

// ---------------- prep kernels ----------------
__global__ void to_half_kernel(const float* __restrict__ src, int which) {
    size_t i = (size_t)blockIdx.x * blockDim.x + threadIdx.x;   // 8-float unit
    float4 v0 = ((const float4*)src)[i * 2];
    float4 v1 = ((const float4*)src)[i * 2 + 1];
    __half2 h[4];
    h[0] = __floats2half2_rn(v0.x, v0.y);
    h[1] = __floats2half2_rn(v0.z, v0.w);
    h[2] = __floats2half2_rn(v1.x, v1.y);
    h[3] = __floats2half2_rn(v1.z, v1.w);
    uint2* dst = which ? (uint2*)g_eh : (uint2*)g_zh;
    dst[i * 2]     = make_uint2(*(uint32_t*)&h[0], *(uint32_t*)&h[1]);
    dst[i * 2 + 1] = make_uint2(*(uint32_t*)&h[2], *(uint32_t*)&h[3]);
}

__global__ void row_norm_kernel(const float* __restrict__ x, int which) {
    int row  = blockIdx.x * 8 + (threadIdx.x >> 5);
    int lane = threadIdx.x & 31;
    const float* p = x + (size_t)row * DD;
    double s = 0.0;
    #pragma unroll
    for (int i = 0; i < DD / 32; ++i) {
        float v = p[lane + i * 32];
        float q = v * v;
        s += (double)q;
    }
    #pragma unroll
    for (int o = 16; o; o >>= 1) s += __shfl_xor_sync(0xffffffffu, s, o);
    if (lane == 0) { if (which) g_e2[row] = (float)s; else g_z2[row] = (float)s; }
}

// ---------------- main: fp16 HFMA2 screen + exact fp32 rescore ----------------
__global__ void __launch_bounds__(256, 1)
vq_h2_kernel(const float* __restrict__ zf, const float* __restrict__ ef) {
    extern __shared__ char smem[];
    uint32_t* As = (uint32_t*)(smem + SM_A);    // [d2][m]
    uint32_t* Bs = (uint32_t*)(smem + SM_B);    // [buf][dl][n]
    uint16_t* candA = (uint16_t*)(smem + SM_CAND);

    int tid = threadIdx.x;
    int tx = tid & 15, ty = tid >> 4;
    int mBase = blockIdx.x * BM;

    if (tid == 0) *(int*)(smem + SM_OVFN) = 0;

    // ---- fill As[d2][m] from fp16 z rows ----
    {
        const __half* zh = g_zh + (size_t)mBase * DD;
        #pragma unroll
        for (int it = 0; it < 16; ++it) {
            int lin = tid + it * 256;          // 0..4095
            int m = lin >> 5, u = lin & 31;    // uint4 (8 halves = 4 d2) idx
            uint4 v = ((const uint4*)(zh + (size_t)m * DD))[u];
            As[(u * 4 + 0) * BM + m] = v.x;
            As[(u * 4 + 1) * BM + m] = v.y;
            As[(u * 4 + 2) * BM + m] = v.z;
            As[(u * 4 + 3) * BM + m] = v.w;
        }
    }

    float runmin[8];
    int   cnt[8];
    #pragma unroll
    for (int i = 0; i < 8; ++i) { runmin[i] = __int_as_float(0x7f800000); cnt[i] = 0; }

    __syncthreads();

    for (int t = 0; t < NTT; ++t) {
        __half2 acc[8][16];
        #pragma unroll
        for (int i = 0; i < 8; ++i)
            #pragma unroll
            for (int j = 0; j < 16; ++j) acc[i][j] = __half2half2(__ushort_as_half(0));

        const __half* et = g_eh + (size_t)t * BN * DD;   // 256 n rows
        // prefetch chunk 0: this thread owns n = tid, 32B (2 uint4) per chunk
        const uint4* ep = (const uint4*)(et + (size_t)tid * DD);
        uint4 p0 = ep[0], p1 = ep[1];
        {
            uint32_t* Bn = Bs;
            Bn[0 * BN + tid] = p0.x; Bn[1 * BN + tid] = p0.y;
            Bn[2 * BN + tid] = p0.z; Bn[3 * BN + tid] = p0.w;
            Bn[4 * BN + tid] = p1.x; Bn[5 * BN + tid] = p1.y;
            Bn[6 * BN + tid] = p1.z; Bn[7 * BN + tid] = p1.w;
        }
        __syncthreads();

        #pragma unroll 1
        for (int c = 0; c < NCH; ++c) {
            const uint32_t* Bc = Bs + (c & 1) * (8 * BN);
            if (c + 1 < NCH) { p0 = ep[(c + 1) * 2]; p1 = ep[(c + 1) * 2 + 1]; }
            #pragma unroll
            for (int dl = 0; dl < 8; ++dl) {
                int d2 = c * 8 + dl;
                const uint32_t* Ar = As + d2 * BM + ty * 8;
                uint4 a0 = *(const uint4*)Ar;
                uint4 a1 = *(const uint4*)(Ar + 4);
                __half2 a[8];
                a[0] = *(__half2*)&a0.x; a[1] = *(__half2*)&a0.y;
                a[2] = *(__half2*)&a0.z; a[3] = *(__half2*)&a0.w;
                a[4] = *(__half2*)&a1.x; a[5] = *(__half2*)&a1.y;
                a[6] = *(__half2*)&a1.z; a[7] = *(__half2*)&a1.w;
                #pragma unroll
                for (int jg = 0; jg < 4; ++jg) {
                    uint4 bv = *(const uint4*)(Bc + dl * BN + jg * 64 + tx * 4);
                    __half2 b[4];
                    b[0] = *(__half2*)&bv.x; b[1] = *(__half2*)&bv.y;
                    b[2] = *(__half2*)&bv.z; b[3] = *(__half2*)&bv.w;
                    #pragma unroll
                    for (int i = 0; i < 8; ++i) {
                        acc[i][jg*4+0] = __hfma2(a[i], b[0], acc[i][jg*4+0]);
                        acc[i][jg*4+1] = __hfma2(a[i], b[1], acc[i][jg*4+1]);
                        acc[i][jg*4+2] = __hfma2(a[i], b[2], acc[i][jg*4+2]);
                        acc[i][jg*4+3] = __hfma2(a[i], b[3], acc[i][jg*4+3]);
                    }
                }
            }
            if (c + 1 < NCH) {
                uint32_t* Bn = Bs + ((c + 1) & 1) * (8 * BN);
                Bn[0 * BN + tid] = p0.x; Bn[1 * BN + tid] = p0.y;
                Bn[2 * BN + tid] = p0.z; Bn[3 * BN + tid] = p0.w;
                Bn[4 * BN + tid] = p1.x; Bn[5 * BN + tid] = p1.y;
                Bn[6 * BN + tid] = p1.z; Bn[7 * BN + tid] = p1.w;
            }
            __syncthreads();
        }

        // tile 0: min-only pre-pass so thresholds are finite
        if (t == 0) {
            #pragma unroll
            for (int j = 0; j < 16; ++j) {
                int k = j >> 2, q = j & 3;
                float e2k = g_e2[t * BN + k * 64 + tx * 4 + q];
                #pragma unroll
                for (int i = 0; i < 8; ++i) {
                    float2 s2 = __half22float2(acc[i][j]);
                    float sc = fmaf(-2.0f, s2.x + s2.y, e2k);
                    runmin[i] = fminf(runmin[i], sc);
                }
            }
            #pragma unroll
            for (int i = 0; i < 8; ++i) {
                float v = runmin[i];
                #pragma unroll
                for (int o = 1; o < 16; o <<= 1)
                    v = fminf(v, __shfl_xor_sync(0xffffffffu, v, o));
                runmin[i] = v;
            }
        }

        float thr[8];
        #pragma unroll
        for (int i = 0; i < 8; ++i) thr[i] = runmin[i] + MARGIN;

        #pragma unroll
        for (int j = 0; j < 16; ++j) {
            int kq = j >> 2, q = j & 3;
            int k = t * BN + kq * 64 + tx * 4 + q;
            float e2k = g_e2[k];
            #pragma unroll
            for (int i = 0; i < 8; ++i) {
                float2 s2 = __half22float2(acc[i][j]);
                float sc = fmaf(-2.0f, s2.x + s2.y, e2k);
                if (sc <= thr[i]) {
                    if (cnt[i] < CAP)
                        candA[((ty * 8 + i) * 16 + tx) * CAP + cnt[i]] = (uint16_t)k;
                    cnt[i]++;
                }
                runmin[i] = fminf(runmin[i], sc);
            }
        }
        #pragma unroll
        for (int i = 0; i < 8; ++i) {
            float v = runmin[i];
            #pragma unroll
            for (int o = 1; o < 16; o <<= 1)
                v = fminf(v, __shfl_xor_sync(0xffffffffu, v, o));
            runmin[i] = v;
        }
    }

    // publish counts
    #pragma unroll
    for (int i = 0; i < 8; ++i)
        ((uint8_t*)(smem + SM_CNT))[(ty * 8 + i) * 16 + tx] =
            (uint8_t)(cnt[i] > CAP ? CAP + 1 : cnt[i]);
    __syncthreads();

    // ---- exact fp32 rescore (verbatim R4 arithmetic) ----
    if (tid < BM) {
        int rr = tid;
        int rowG = mBase + rr;
        const uint8_t* cp = (const uint8_t*)(smem + SM_CNT) + rr * 16;
        bool ovf = false;
        #pragma unroll
        for (int s = 0; s < 16; ++s) ovf |= (cp[s] > CAP);
        if (ovf) {
            int s = atomicAdd((int*)(smem + SM_OVFN), 1);
            ((int*)(smem + SM_OVFR))[s] = rr;
        } else {
            const float* zr = zf + (size_t)rowG * DD;
            float z2 = g_z2[rowG];
            uint32_t bestBits = 0xffffffffu; int bestK = 0;
            for (int s = 0; s < 16; ++s) {
                int c = cp[s];
                for (int i2 = 0; i2 < c; ++i2) {
                    int k = candA[(rr * 16 + s) * CAP + i2];
                    const float* er = ef + (size_t)k * DD;
                    float dot = 0.0f;
                    #pragma unroll 4
                    for (int d4 = 0; d4 < DD / 4; ++d4) {
                        float4 zv = ((const float4*)zr)[d4];
                        float4 ev = ((const float4*)er)[d4];
                        dot = fmaf(zv.x, ev.x, dot);
                        dot = fmaf(zv.y, ev.y, dot);
                        dot = fmaf(zv.z, ev.z, dot);
                        dot = fmaf(zv.w, ev.w, dot);
                    }
                    float t1 = z2 + g_e2[k];
                    float dist = t1 - 2.0f * dot;
                    uint32_t bits = __float_as_uint(dist);
                    if (bits < bestBits || (bits == bestBits && k < bestK)) {
                        bestBits = bits; bestK = k;
                    }
                }
            }
            g_idx[rowG] = bestK;
        }
    }
    __syncthreads();

    // ---- rare overflow fallback: cooperative exact full-row scan ----
    int novf = *(int*)(smem + SM_OVFN);
    unsigned long long* pack = (unsigned long long*)(smem + SM_PACK);
    for (int o = 0; o < novf; ++o) {
        int rr = ((int*)(smem + SM_OVFR))[o];
        int rG = mBase + rr;
        if (tid == 0) *pack = 0xffffffffffffffffULL;
        __syncthreads();
        const float* zr = zf + (size_t)rG * DD;
        float z2 = g_z2[rG];
        for (int k = tid; k < KK; k += 256) {
            const float* er = ef + (size_t)k * DD;
            float dot = 0.0f;
            #pragma unroll 4
            for (int d4 = 0; d4 < DD / 4; ++d4) {
                float4 zv = ((const float4*)zr)[d4];
                float4 ev = ((const float4*)er)[d4];
                dot = fmaf(zv.x, ev.x, dot);
                dot = fmaf(zv.y, ev.y, dot);
                dot = fmaf(zv.z, ev.z, dot);
                dot = fmaf(zv.w, ev.w, dot);
            }
            float t1 = z2 + g_e2[k];
            float dist = t1 - 2.0f * dot;
            unsigned long long p =
                ((unsigned long long)__float_as_uint(dist) << 32) | (unsigned)k;
            atomicMin(pack, p);
        }
        __syncthreads();
        if (tid == 0) g_idx[rG] = (int)(*pack & 0xffffffffu);
        __syncthreads();
    }
}

// ---------------- gather + writeout ----------------
__global__ void writeout_kernel(const float* __restrict__ e, float* __restrict__ out,
                                long long q_off, long long st_off, long long idx_off) {
    int row  = blockIdx.x * 8 + (threadIdx.x >> 5);
    int lane = threadIdx.x & 31;
    int idx  = g_idx[row];
    const float4* src = (const float4*)(e + (size_t)idx * DD);
    #pragma unroll
    for (int i = 0; i < 2; ++i) {
        float4 v = src[lane + i * 32];
        if (q_off >= 0)  ((float4*)(out + q_off))[(size_t)row * 64 + lane + i * 32] = v;
        if (st_off >= 0) ((float4*)(out + st_off))[(size_t)row * 64 + lane + i * 32] = v;
    }
    if (idx_off >= 0 && lane == 0) out[idx_off + row] = (float)idx;
}

extern "C" void kernel_launch(void* const* d_in, const int* in_sizes, int n_in,
                              void* d_out, int out_size) {
    const float* z = (const float*)d_in[0];
    const float* e = (const float*)d_in[1];
    float* out = (float*)d_out;

    cudaFuncSetAttribute(vq_h2_kernel,
                         cudaFuncAttributeMaxDynamicSharedMemorySize, SMEM_BYTES);

    to_half_kernel<<<(NN * DD / 8) / 256, 256>>>(z, 0);
    to_half_kernel<<<(KK * DD / 8) / 256, 256>>>(e, 1);
    row_norm_kernel<<<NN / 8, 256>>>(z, 0);
    row_norm_kernel<<<KK / 8, 256>>>(e, 1);

    vq_h2_kernel<<<NN / BM, 256, SMEM_BYTES>>>(z, e);

    long long sz = out_size, pos = 0;
    long long q_off = -1, st_off = -1, idx_off = -1;
    if (sz - pos >= (long long)NN * DD) { q_off = pos;  pos += (long long)NN * DD; }
    if (sz - pos >= (long long)NN * DD) { st_off = pos; pos += (long long)NN * DD; }
    if (sz - pos >= NN)                 { idx_off = pos; }
    writeout_kernel<<<NN / 8, 256>>>(e, out, q_off, st_off, idx_off);
}

// round 6
// speedup vs baseline: 7.2069x; 7.0142x over previous
#include <cuda_runtime.h>
#include <cuda_fp16.h>
#include <cstdint>

#define NN 65536
#define KK 8192
#define DD 256
#define BM 128
#define BN 128
#define NTT (KK/BN)      // 64 n-tiles
#define NCH 16           // chunks of 8 d2 (16 d) each
#define MARGIN 1.5e-3f
#define CAP 8

// smem byte offsets
#define SM_A     0          // u32[128 d2][128 m]            65536
#define SM_B     65536      // u32[2][8 dl][128 n]            8192
#define SM_CAND  73728      // u16[128 m][16 tx][CAP]        32768
#define SM_CNT   106496     // u8[128][16]                    2048
#define SM_OVFN  108544
#define SM_OVFR  108548     // int[128]
#define SM_PACK  109064     // 8B aligned
#define SMEM_BYTES 109072

__device__ float g_z2[NN];
__device__ float g_e2[KK];
__device__ int   g_idx[NN];
__device__ __half    g_zh[(size_t)NN * DD];
__device__ uint32_t  g_ehT[(size_t)(DD/2) * KK];   // [d2][k] half2-as-u32

// ---------------- prep kernels ----------------
__global__ void to_half_kernel(const float* __restrict__ src) {
    size_t i = (size_t)blockIdx.x * blockDim.x + threadIdx.x;   // 8-float unit
    float4 v0 = ((const float4*)src)[i * 2];
    float4 v1 = ((const float4*)src)[i * 2 + 1];
    __half2 h0 = __floats2half2_rn(v0.x, v0.y);
    __half2 h1 = __floats2half2_rn(v0.z, v0.w);
    __half2 h2 = __floats2half2_rn(v1.x, v1.y);
    __half2 h3 = __floats2half2_rn(v1.z, v1.w);
    uint2* dst = (uint2*)g_zh;
    dst[i * 2]     = make_uint2(*(uint32_t*)&h0, *(uint32_t*)&h1);
    dst[i * 2 + 1] = make_uint2(*(uint32_t*)&h2, *(uint32_t*)&h3);
}

// e[k][d] fp32 -> g_ehT[d2][k] half2, staged through smem for coalesced I/O
__global__ void transpose_e_kernel(const float* __restrict__ e) {
    __shared__ uint32_t ts[128][33];
    int tid = threadIdx.x, wid = tid >> 5, lane = tid & 31;
    int k0 = blockIdx.x * 32;
    #pragma unroll
    for (int r = 0; r < 4; ++r) {
        int k = k0 + wid * 4 + r;
        const float4* row = (const float4*)(e + (size_t)k * DD);
        #pragma unroll
        for (int h = 0; h < 2; ++h) {
            float4 v = row[lane * 2 + h];
            int d2 = (lane * 2 + h) * 2;
            __half2 ha = __floats2half2_rn(v.x, v.y);
            __half2 hb = __floats2half2_rn(v.z, v.w);
            ts[d2][k - k0]     = *(uint32_t*)&ha;
            ts[d2 + 1][k - k0] = *(uint32_t*)&hb;
        }
    }
    __syncthreads();
    #pragma unroll
    for (int it = 0; it < 16; ++it) {
        int lin = tid + it * 256;
        int d2 = lin >> 5, kl = lin & 31;
        g_ehT[(size_t)d2 * KK + k0 + kl] = ts[d2][kl];
    }
}

__global__ void row_norm_kernel(const float* __restrict__ x, int which) {
    int row  = blockIdx.x * 8 + (threadIdx.x >> 5);
    int lane = threadIdx.x & 31;
    const float* p = x + (size_t)row * DD;
    double s = 0.0;
    #pragma unroll
    for (int i = 0; i < DD / 32; ++i) {
        float v = p[lane + i * 32];
        float q = v * v;
        s += (double)q;
    }
    #pragma unroll
    for (int o = 16; o; o >>= 1) s += __shfl_xor_sync(0xffffffffu, s, o);
    if (lane == 0) { if (which) g_e2[row] = (float)s; else g_z2[row] = (float)s; }
}

// ---------------- main: fp16 HFMA2 screen + exact fp32 rescore ----------------
__global__ void __launch_bounds__(256, 1)
vq_h2_kernel(const float* __restrict__ zf, const float* __restrict__ ef) {
    extern __shared__ char smem[];
    uint32_t* As = (uint32_t*)(smem + SM_A);    // [d2][m]
    uint32_t* Bs = (uint32_t*)(smem + SM_B);    // [buf][dl][n]
    uint16_t* candA = (uint16_t*)(smem + SM_CAND);

    int tid = threadIdx.x;
    int tx = tid & 15, ty = tid >> 4;
    int mBase = blockIdx.x * BM;

    if (tid == 0) *(int*)(smem + SM_OVFN) = 0;

    // ---- fill As[d2][m] from fp16 z rows (coalesced LDG; one-time STS conflicts OK) ----
    {
        const __half* zh = g_zh + (size_t)mBase * DD;
        #pragma unroll
        for (int it = 0; it < 16; ++it) {
            int lin = tid + it * 256;          // 0..4095
            int m = lin >> 5, u = lin & 31;    // uint4 (8 halves = 4 d2) idx
            uint4 v = ((const uint4*)(zh + (size_t)m * DD))[u];
            As[(u * 4 + 0) * BM + m] = v.x;
            As[(u * 4 + 1) * BM + m] = v.y;
            As[(u * 4 + 2) * BM + m] = v.z;
            As[(u * 4 + 3) * BM + m] = v.w;
        }
    }

    float runmin[8];
    int   cnt[8];
    #pragma unroll
    for (int i = 0; i < 8; ++i) { runmin[i] = __int_as_float(0x7f800000); cnt[i] = 0; }

    __syncthreads();

    int dl0 = tid >> 5, nq = (tid & 31) * 4;   // this thread's B-fill slot

    #pragma unroll 1
    for (int t = 0; t < NTT; ++t) {
        __half2 acc[8][8];
        #pragma unroll
        for (int i = 0; i < 8; ++i)
            #pragma unroll
            for (int j = 0; j < 8; ++j) acc[i][j] = __half2half2(__ushort_as_half(0));

        // chunk source: g_ehT[(c*8+dl0)][t*128 + nq .. +3]
        const uint32_t* ebase = g_ehT + (size_t)dl0 * KK + t * BN + nq;
        uint4 p = *(const uint4*)ebase;                      // chunk 0
        *(uint4*)(Bs + dl0 * BN + nq) = p;
        __syncthreads();

        #pragma unroll 1
        for (int c = 0; c < NCH; ++c) {
            const uint32_t* Bc = Bs + (c & 1) * (8 * BN);
            if (c + 1 < NCH) p = *(const uint4*)(ebase + (size_t)(c + 1) * 8 * KK);
            #pragma unroll
            for (int dl = 0; dl < 8; ++dl) {
                const uint32_t* Ar = As + (c * 8 + dl) * BM + ty * 8;
                uint4 a0 = *(const uint4*)Ar;
                uint4 a1 = *(const uint4*)(Ar + 4);
                __half2 a[8];
                a[0] = *(__half2*)&a0.x; a[1] = *(__half2*)&a0.y;
                a[2] = *(__half2*)&a0.z; a[3] = *(__half2*)&a0.w;
                a[4] = *(__half2*)&a1.x; a[5] = *(__half2*)&a1.y;
                a[6] = *(__half2*)&a1.z; a[7] = *(__half2*)&a1.w;
                const uint32_t* Br = Bc + dl * BN + tx * 8;
                uint4 b0 = *(const uint4*)Br;
                uint4 b1 = *(const uint4*)(Br + 4);
                __half2 b[8];
                b[0] = *(__half2*)&b0.x; b[1] = *(__half2*)&b0.y;
                b[2] = *(__half2*)&b0.z; b[3] = *(__half2*)&b0.w;
                b[4] = *(__half2*)&b1.x; b[5] = *(__half2*)&b1.y;
                b[6] = *(__half2*)&b1.z; b[7] = *(__half2*)&b1.w;
                #pragma unroll
                for (int i = 0; i < 8; ++i)
                    #pragma unroll
                    for (int j = 0; j < 8; ++j)
                        acc[i][j] = __hfma2(a[i], b[j], acc[i][j]);
            }
            if (c + 1 < NCH)
                *(uint4*)(Bs + ((c + 1) & 1) * (8 * BN) + dl0 * BN + nq) = p;
            __syncthreads();
        }

        // tile 0: min-only pre-pass so thresholds are finite
        const float4* e2p = (const float4*)(g_e2 + t * BN + tx * 8);
        float4 e2v0 = e2p[0], e2v1 = e2p[1];
        float e2a[8] = {e2v0.x, e2v0.y, e2v0.z, e2v0.w, e2v1.x, e2v1.y, e2v1.z, e2v1.w};

        if (t == 0) {
            #pragma unroll
            for (int j = 0; j < 8; ++j)
                #pragma unroll
                for (int i = 0; i < 8; ++i) {
                    float2 s2 = __half22float2(acc[i][j]);
                    float sc = fmaf(-2.0f, s2.x + s2.y, e2a[j]);
                    runmin[i] = fminf(runmin[i], sc);
                }
            #pragma unroll
            for (int i = 0; i < 8; ++i) {
                float v = runmin[i];
                #pragma unroll
                for (int o = 1; o < 16; o <<= 1)
                    v = fminf(v, __shfl_xor_sync(0xffffffffu, v, o));
                runmin[i] = v;
            }
        }

        float thr[8];
        #pragma unroll
        for (int i = 0; i < 8; ++i) thr[i] = runmin[i] + MARGIN;

        #pragma unroll
        for (int j = 0; j < 8; ++j) {
            int k = t * BN + tx * 8 + j;
            #pragma unroll
            for (int i = 0; i < 8; ++i) {
                float2 s2 = __half22float2(acc[i][j]);
                float sc = fmaf(-2.0f, s2.x + s2.y, e2a[j]);
                if (sc <= thr[i]) {
                    if (cnt[i] < CAP)
                        candA[((ty * 8 + i) * 16 + tx) * CAP + cnt[i]] = (uint16_t)k;
                    cnt[i]++;
                }
                runmin[i] = fminf(runmin[i], sc);
            }
        }
        #pragma unroll
        for (int i = 0; i < 8; ++i) {
            float v = runmin[i];
            #pragma unroll
            for (int o = 1; o < 16; o <<= 1)
                v = fminf(v, __shfl_xor_sync(0xffffffffu, v, o));
            runmin[i] = v;
        }
    }

    // publish counts
    #pragma unroll
    for (int i = 0; i < 8; ++i)
        ((uint8_t*)(smem + SM_CNT))[(ty * 8 + i) * 16 + tx] =
            (uint8_t)(cnt[i] > CAP ? CAP + 1 : cnt[i]);
    __syncthreads();

    // ---- exact fp32 rescore (verbatim proven arithmetic) ----
    if (tid < BM) {
        int rr = tid;
        int rowG = mBase + rr;
        const uint8_t* cp = (const uint8_t*)(smem + SM_CNT) + rr * 16;
        bool ovf = false;
        #pragma unroll
        for (int s = 0; s < 16; ++s) ovf |= (cp[s] > CAP);
        if (ovf) {
            int s = atomicAdd((int*)(smem + SM_OVFN), 1);
            ((int*)(smem + SM_OVFR))[s] = rr;
        } else {
            const float* zr = zf + (size_t)rowG * DD;
            float z2 = g_z2[rowG];
            uint32_t bestBits = 0xffffffffu; int bestK = 0;
            for (int s = 0; s < 16; ++s) {
                int c = cp[s];
                for (int i2 = 0; i2 < c; ++i2) {
                    int k = candA[(rr * 16 + s) * CAP + i2];
                    const float* er = ef + (size_t)k * DD;
                    float dot = 0.0f;
                    #pragma unroll 4
                    for (int d4 = 0; d4 < DD / 4; ++d4) {
                        float4 zv = ((const float4*)zr)[d4];
                        float4 ev = ((const float4*)er)[d4];
                        dot = fmaf(zv.x, ev.x, dot);
                        dot = fmaf(zv.y, ev.y, dot);
                        dot = fmaf(zv.z, ev.z, dot);
                        dot = fmaf(zv.w, ev.w, dot);
                    }
                    float t1 = z2 + g_e2[k];
                    float dist = t1 - 2.0f * dot;
                    uint32_t bits = __float_as_uint(dist);
                    if (bits < bestBits || (bits == bestBits && k < bestK)) {
                        bestBits = bits; bestK = k;
                    }
                }
            }
            g_idx[rowG] = bestK;
        }
    }
    __syncthreads();

    // ---- rare overflow fallback: cooperative exact full-row scan ----
    int novf = *(int*)(smem + SM_OVFN);
    unsigned long long* pack = (unsigned long long*)(smem + SM_PACK);
    for (int o = 0; o < novf; ++o) {
        int rr = ((int*)(smem + SM_OVFR))[o];
        int rG = mBase + rr;
        if (tid == 0) *pack = 0xffffffffffffffffULL;
        __syncthreads();
        const float* zr = zf + (size_t)rG * DD;
        float z2 = g_z2[rG];
        for (int k = tid; k < KK; k += 256) {
            const float* er = ef + (size_t)k * DD;
            float dot = 0.0f;
            #pragma unroll 4
            for (int d4 = 0; d4 < DD / 4; ++d4) {
                float4 zv = ((const float4*)zr)[d4];
                float4 ev = ((const float4*)er)[d4];
                dot = fmaf(zv.x, ev.x, dot);
                dot = fmaf(zv.y, ev.y, dot);
                dot = fmaf(zv.z, ev.z, dot);
                dot = fmaf(zv.w, ev.w, dot);
            }
            float t1 = z2 + g_e2[k];
            float dist = t1 - 2.0f * dot;
            unsigned long long pq =
                ((unsigned long long)__float_as_uint(dist) << 32) | (unsigned)k;
            atomicMin(pack, pq);
        }
        __syncthreads();
        if (tid == 0) g_idx[rG] = (int)(*pack & 0xffffffffu);
        __syncthreads();
    }
}

// ---------------- gather + writeout ----------------
__global__ void writeout_kernel(const float* __restrict__ e, float* __restrict__ out,
                                long long q_off, long long st_off, long long idx_off) {
    int row  = blockIdx.x * 8 + (threadIdx.x >> 5);
    int lane = threadIdx.x & 31;
    int idx  = g_idx[row];
    const float4* src = (const float4*)(e + (size_t)idx * DD);
    #pragma unroll
    for (int i = 0; i < 2; ++i) {
        float4 v = src[lane + i * 32];
        if (q_off >= 0)  ((float4*)(out + q_off))[(size_t)row * 64 + lane + i * 32] = v;
        if (st_off >= 0) ((float4*)(out + st_off))[(size_t)row * 64 + lane + i * 32] = v;
    }
    if (idx_off >= 0 && lane == 0) out[idx_off + row] = (float)idx;
}

extern "C" void kernel_launch(void* const* d_in, const int* in_sizes, int n_in,
                              void* d_out, int out_size) {
    const float* z = (const float*)d_in[0];
    const float* e = (const float*)d_in[1];
    float* out = (float*)d_out;

    cudaFuncSetAttribute(vq_h2_kernel,
                         cudaFuncAttributeMaxDynamicSharedMemorySize, SMEM_BYTES);

    to_half_kernel<<<(NN * DD / 8) / 256, 256>>>(z);
    transpose_e_kernel<<<KK / 32, 256>>>(e);
    row_norm_kernel<<<NN / 8, 256>>>(z, 0);
    row_norm_kernel<<<KK / 8, 256>>>(e, 1);

    vq_h2_kernel<<<NN / BM, 256, SMEM_BYTES>>>(z, e);

    long long sz = out_size, pos = 0;
    long long q_off = -1, st_off = -1, idx_off = -1;
    if (sz - pos >= (long long)NN * DD) { q_off = pos;  pos += (long long)NN * DD; }
    if (sz - pos >= (long long)NN * DD) { st_off = pos; pos += (long long)NN * DD; }
    if (sz - pos >= NN)                 { idx_off = pos; }
    writeout_kernel<<<NN / 8, 256>>>(e, out, q_off, st_off, idx_off);
}

// round 7
// speedup vs baseline: 36.3338x; 5.0415x over previous
#include <cuda_runtime.h>
#include <cstdint>

#define NN 65536
#define KK 8192
#define DD 256
#define BM 128
#define BN 128
#define NTT (KK/BN)      // 64 n-tiles
#define NCH 8            // chunks of 8 d4 (32 dims)
#define MARGIN 6.0e-4f
#define CAP 8

// smem byte offsets
#define SM_A     0          // u32[64 d4][128 m]             32768
#define SM_B     32768      // u32[2][8 dl][128 n]            8192
#define SM_CAND  40960      // u16[128 m][16 tx][CAP]        32768
#define SM_CNT   73728      // u8[128][16]                    2048
#define SM_OVFN  75776
#define SM_OVFR  75780      // int[128]
#define SM_PACK  76296      // 8B aligned
#define SMEM_BYTES 76304

__device__ float    g_z2[NN];
__device__ float    g_e2[KK];
__device__ float    g_sz[NN];        // z row scale (amax/127)
__device__ float    g_se2[KK];       // -2 * e row scale
__device__ int      g_idx[NN];
__device__ uint32_t g_zq[(size_t)NN * (DD/4)];          // packed int8 [n][d4]
__device__ uint32_t g_eqT[(size_t)(DD/4) * KK];         // packed int8 [d4][k]

// ---------------- prep kernels ----------------
// row_norm: UNCHANGED from proven rounds (g_z2/g_e2 bit-identical).
__global__ void row_norm_kernel(const float* __restrict__ x, int which) {
    int row  = blockIdx.x * 8 + (threadIdx.x >> 5);
    int lane = threadIdx.x & 31;
    const float* p = x + (size_t)row * DD;
    double s = 0.0;
    #pragma unroll
    for (int i = 0; i < DD / 32; ++i) {
        float v = p[lane + i * 32];
        float q = v * v;
        s += (double)q;
    }
    #pragma unroll
    for (int o = 16; o; o >>= 1) s += __shfl_xor_sync(0xffffffffu, s, o);
    if (lane == 0) { if (which) g_e2[row] = (float)s; else g_z2[row] = (float)s; }
}

__device__ __forceinline__ uint32_t pack4(const float* v, float qs) {
    uint32_t r = 0;
    #pragma unroll
    for (int i = 0; i < 4; ++i) {
        int q = __float2int_rn(v[i] * qs);
        q = max(-127, min(127, q));
        r |= (uint32_t)(q & 0xff) << (i * 8);
    }
    return r;
}

__global__ void quant_z_kernel(const float* __restrict__ x) {
    int row  = blockIdx.x * 8 + (threadIdx.x >> 5);
    int lane = threadIdx.x & 31;
    const float4* p = (const float4*)(x + (size_t)row * DD);
    float4 v0 = p[lane * 2], v1 = p[lane * 2 + 1];
    float v[8] = {v0.x, v0.y, v0.z, v0.w, v1.x, v1.y, v1.z, v1.w};
    float amax = 0.0f;
    #pragma unroll
    for (int i = 0; i < 8; ++i) amax = fmaxf(amax, fabsf(v[i]));
    #pragma unroll
    for (int o = 16; o; o >>= 1) amax = fmaxf(amax, __shfl_xor_sync(0xffffffffu, amax, o));
    float qs = amax > 0.0f ? 127.0f / amax : 0.0f;
    g_zq[(size_t)row * 64 + lane * 2]     = pack4(v, qs);
    g_zq[(size_t)row * 64 + lane * 2 + 1] = pack4(v + 4, qs);
    if (lane == 0) g_sz[row] = amax * (1.0f / 127.0f);
}

__global__ void quant_eT_kernel(const float* __restrict__ e) {
    __shared__ uint32_t ts[64][33];
    int tid = threadIdx.x, wid = tid >> 5, lane = tid & 31;
    int k0 = blockIdx.x * 32;
    #pragma unroll
    for (int r = 0; r < 4; ++r) {
        int kl = wid * 4 + r;
        int k = k0 + kl;
        const float4* p = (const float4*)(e + (size_t)k * DD);
        float4 v0 = p[lane * 2], v1 = p[lane * 2 + 1];
        float v[8] = {v0.x, v0.y, v0.z, v0.w, v1.x, v1.y, v1.z, v1.w};
        float amax = 0.0f;
        #pragma unroll
        for (int i = 0; i < 8; ++i) amax = fmaxf(amax, fabsf(v[i]));
        #pragma unroll
        for (int o = 16; o; o >>= 1) amax = fmaxf(amax, __shfl_xor_sync(0xffffffffu, amax, o));
        float qs = amax > 0.0f ? 127.0f / amax : 0.0f;
        ts[lane * 2][kl]     = pack4(v, qs);
        ts[lane * 2 + 1][kl] = pack4(v + 4, qs);
        if (lane == 0) g_se2[k] = -2.0f * amax * (1.0f / 127.0f);
    }
    __syncthreads();
    #pragma unroll
    for (int it = 0; it < 8; ++it) {
        int lin = tid + it * 256;
        int d4 = lin >> 5, kl = lin & 31;
        g_eqT[(size_t)d4 * KK + k0 + kl] = ts[d4][kl];
    }
}

// ---------------- main: int8 dp4a screen + exact fp32 rescore ----------------
__global__ void __launch_bounds__(256, 1)
vq_dp4a_kernel(const float* __restrict__ zf, const float* __restrict__ ef) {
    extern __shared__ char smem[];
    uint32_t* As = (uint32_t*)(smem + SM_A);    // [d4][m]
    uint32_t* Bs = (uint32_t*)(smem + SM_B);    // [buf][dl][n]
    uint16_t* candA = (uint16_t*)(smem + SM_CAND);

    int tid = threadIdx.x;
    int tx = tid & 15, ty = tid >> 4;
    int mBase = blockIdx.x * BM;

    if (tid == 0) *(int*)(smem + SM_OVFN) = 0;

    // ---- fill As[d4][m]: conflict-free STS (lanes span m) ----
    {
        const uint32_t* zq = g_zq + (size_t)mBase * 64;
        #pragma unroll
        for (int it = 0; it < 8; ++it) {
            int lin = tid + it * 256;          // 0..2047
            int m = lin & 127, ug = lin >> 7;  // ug 0..15 (uint4 within row)
            uint4 v = *(const uint4*)(zq + (size_t)m * 64 + ug * 4);
            As[(ug * 4 + 0) * BM + m] = v.x;
            As[(ug * 4 + 1) * BM + m] = v.y;
            As[(ug * 4 + 2) * BM + m] = v.z;
            As[(ug * 4 + 3) * BM + m] = v.w;
        }
    }

    float szr[8];
    #pragma unroll
    for (int i = 0; i < 8; ++i) szr[i] = g_sz[mBase + ty * 8 + i];

    float runmin[8];
    int   cnt[8];
    #pragma unroll
    for (int i = 0; i < 8; ++i) { runmin[i] = __int_as_float(0x7f800000); cnt[i] = 0; }

    __syncthreads();

    int dl0 = tid >> 5, nq = (tid & 31) * 4;   // B-fill slot

    #pragma unroll 1
    for (int t = 0; t < NTT; ++t) {
        int acc[8][8];
        #pragma unroll
        for (int i = 0; i < 8; ++i)
            #pragma unroll
            for (int j = 0; j < 8; ++j) acc[i][j] = 0;

        const uint32_t* ebase = g_eqT + (size_t)dl0 * KK + t * BN + nq;
        uint4 p = *(const uint4*)ebase;                      // chunk 0
        *(uint4*)(Bs + dl0 * BN + nq) = p;
        __syncthreads();

        #pragma unroll 1
        for (int c = 0; c < NCH; ++c) {
            const uint32_t* Bc = Bs + (c & 1) * (8 * BN);
            if (c + 1 < NCH) p = *(const uint4*)(ebase + (size_t)(c + 1) * 8 * KK);
            #pragma unroll
            for (int dl = 0; dl < 8; ++dl) {
                const uint32_t* Ar = As + (c * 8 + dl) * BM + ty * 8;
                uint4 a0 = *(const uint4*)Ar;
                uint4 a1 = *(const uint4*)(Ar + 4);
                const uint32_t* Br = Bc + dl * BN + tx * 8;
                uint4 b0 = *(const uint4*)Br;
                uint4 b1 = *(const uint4*)(Br + 4);
                int aa[8] = {(int)a0.x, (int)a0.y, (int)a0.z, (int)a0.w,
                             (int)a1.x, (int)a1.y, (int)a1.z, (int)a1.w};
                int bb[8] = {(int)b0.x, (int)b0.y, (int)b0.z, (int)b0.w,
                             (int)b1.x, (int)b1.y, (int)b1.z, (int)b1.w};
                #pragma unroll
                for (int i = 0; i < 8; ++i)
                    #pragma unroll
                    for (int j = 0; j < 8; ++j)
                        acc[i][j] = __dp4a(aa[i], bb[j], acc[i][j]);
            }
            if (c + 1 < NCH)
                *(uint4*)(Bs + ((c + 1) & 1) * (8 * BN) + dl0 * BN + nq) = p;
            __syncthreads();
        }

        // epilogue: score = fmaf(sz_i * se2_j, (float)idot, e2_k)
        const float4* se2p = (const float4*)(g_se2 + t * BN + tx * 8);
        float4 s20 = se2p[0], s21 = se2p[1];
        float se2a[8] = {s20.x, s20.y, s20.z, s20.w, s21.x, s21.y, s21.z, s21.w};
        const float4* e2p = (const float4*)(g_e2 + t * BN + tx * 8);
        float4 e20 = e2p[0], e21 = e2p[1];
        float e2a[8] = {e20.x, e20.y, e20.z, e20.w, e21.x, e21.y, e21.z, e21.w};

        if (t == 0) {     // min-only pre-pass so thresholds are finite
            #pragma unroll
            for (int j = 0; j < 8; ++j)
                #pragma unroll
                for (int i = 0; i < 8; ++i) {
                    float sc = fmaf(szr[i] * se2a[j], (float)acc[i][j], e2a[j]);
                    runmin[i] = fminf(runmin[i], sc);
                }
            #pragma unroll
            for (int i = 0; i < 8; ++i) {
                float v = runmin[i];
                #pragma unroll
                for (int o = 1; o < 16; o <<= 1)
                    v = fminf(v, __shfl_xor_sync(0xffffffffu, v, o));
                runmin[i] = v;
            }
        }

        float thr[8];
        #pragma unroll
        for (int i = 0; i < 8; ++i) thr[i] = runmin[i] + MARGIN;

        #pragma unroll
        for (int j = 0; j < 8; ++j) {
            int k = t * BN + tx * 8 + j;
            #pragma unroll
            for (int i = 0; i < 8; ++i) {
                float sc = fmaf(szr[i] * se2a[j], (float)acc[i][j], e2a[j]);
                if (sc <= thr[i]) {
                    if (cnt[i] < CAP)
                        candA[((ty * 8 + i) * 16 + tx) * CAP + cnt[i]] = (uint16_t)k;
                    cnt[i]++;
                }
                runmin[i] = fminf(runmin[i], sc);
            }
        }
        #pragma unroll
        for (int i = 0; i < 8; ++i) {
            float v = runmin[i];
            #pragma unroll
            for (int o = 1; o < 16; o <<= 1)
                v = fminf(v, __shfl_xor_sync(0xffffffffu, v, o));
            runmin[i] = v;
        }
    }

    // publish counts
    #pragma unroll
    for (int i = 0; i < 8; ++i)
        ((uint8_t*)(smem + SM_CNT))[(ty * 8 + i) * 16 + tx] =
            (uint8_t)(cnt[i] > CAP ? CAP + 1 : cnt[i]);
    __syncthreads();

    // ---- exact fp32 rescore (verbatim proven arithmetic) ----
    if (tid < BM) {
        int rr = tid;
        int rowG = mBase + rr;
        const uint8_t* cp = (const uint8_t*)(smem + SM_CNT) + rr * 16;
        bool ovf = false;
        #pragma unroll
        for (int s = 0; s < 16; ++s) ovf |= (cp[s] > CAP);
        if (ovf) {
            int s = atomicAdd((int*)(smem + SM_OVFN), 1);
            ((int*)(smem + SM_OVFR))[s] = rr;
        } else {
            const float* zr = zf + (size_t)rowG * DD;
            float z2 = g_z2[rowG];
            uint32_t bestBits = 0xffffffffu; int bestK = 0;
            for (int s = 0; s < 16; ++s) {
                int c = cp[s];
                for (int i2 = 0; i2 < c; ++i2) {
                    int k = candA[(rr * 16 + s) * CAP + i2];
                    const float* er = ef + (size_t)k * DD;
                    float dot = 0.0f;
                    #pragma unroll 4
                    for (int d4 = 0; d4 < DD / 4; ++d4) {
                        float4 zv = ((const float4*)zr)[d4];
                        float4 ev = ((const float4*)er)[d4];
                        dot = fmaf(zv.x, ev.x, dot);
                        dot = fmaf(zv.y, ev.y, dot);
                        dot = fmaf(zv.z, ev.z, dot);
                        dot = fmaf(zv.w, ev.w, dot);
                    }
                    float t1 = z2 + g_e2[k];
                    float dist = t1 - 2.0f * dot;
                    uint32_t bits = __float_as_uint(dist);
                    if (bits < bestBits || (bits == bestBits && k < bestK)) {
                        bestBits = bits; bestK = k;
                    }
                }
            }
            g_idx[rowG] = bestK;
        }
    }
    __syncthreads();

    // ---- rare overflow fallback: cooperative exact full-row scan ----
    int novf = *(int*)(smem + SM_OVFN);
    unsigned long long* pack = (unsigned long long*)(smem + SM_PACK);
    for (int o = 0; o < novf; ++o) {
        int rr = ((int*)(smem + SM_OVFR))[o];
        int rG = mBase + rr;
        if (tid == 0) *pack = 0xffffffffffffffffULL;
        __syncthreads();
        const float* zr = zf + (size_t)rG * DD;
        float z2 = g_z2[rG];
        for (int k = tid; k < KK; k += 256) {
            const float* er = ef + (size_t)k * DD;
            float dot = 0.0f;
            #pragma unroll 4
            for (int d4 = 0; d4 < DD / 4; ++d4) {
                float4 zv = ((const float4*)zr)[d4];
                float4 ev = ((const float4*)er)[d4];
                dot = fmaf(zv.x, ev.x, dot);
                dot = fmaf(zv.y, ev.y, dot);
                dot = fmaf(zv.z, ev.z, dot);
                dot = fmaf(zv.w, ev.w, dot);
            }
            float t1 = z2 + g_e2[k];
            float dist = t1 - 2.0f * dot;
            unsigned long long pq =
                ((unsigned long long)__float_as_uint(dist) << 32) | (unsigned)k;
            atomicMin(pack, pq);
        }
        __syncthreads();
        if (tid == 0) g_idx[rG] = (int)(*pack & 0xffffffffu);
        __syncthreads();
    }
}

// ---------------- gather + writeout ----------------
__global__ void writeout_kernel(const float* __restrict__ e, float* __restrict__ out,
                                long long q_off, long long st_off, long long idx_off) {
    int row  = blockIdx.x * 8 + (threadIdx.x >> 5);
    int lane = threadIdx.x & 31;
    int idx  = g_idx[row];
    const float4* src = (const float4*)(e + (size_t)idx * DD);
    #pragma unroll
    for (int i = 0; i < 2; ++i) {
        float4 v = src[lane + i * 32];
        if (q_off >= 0)  ((float4*)(out + q_off))[(size_t)row * 64 + lane + i * 32] = v;
        if (st_off >= 0) ((float4*)(out + st_off))[(size_t)row * 64 + lane + i * 32] = v;
    }
    if (idx_off >= 0 && lane == 0) out[idx_off + row] = (float)idx;
}

extern "C" void kernel_launch(void* const* d_in, const int* in_sizes, int n_in,
                              void* d_out, int out_size) {
    const float* z = (const float*)d_in[0];
    const float* e = (const float*)d_in[1];
    float* out = (float*)d_out;

    cudaFuncSetAttribute(vq_dp4a_kernel,
                         cudaFuncAttributeMaxDynamicSharedMemorySize, SMEM_BYTES);

    row_norm_kernel<<<NN / 8, 256>>>(z, 0);
    row_norm_kernel<<<KK / 8, 256>>>(e, 1);
    quant_z_kernel<<<NN / 8, 256>>>(z);
    quant_eT_kernel<<<KK / 32, 256>>>(e);

    vq_dp4a_kernel<<<NN / BM, 256, SMEM_BYTES>>>(z, e);

    long long sz = out_size, pos = 0;
    long long q_off = -1, st_off = -1, idx_off = -1;
    if (sz - pos >= (long long)NN * DD) { q_off = pos;  pos += (long long)NN * DD; }
    if (sz - pos >= (long long)NN * DD) { st_off = pos; pos += (long long)NN * DD; }
    if (sz - pos >= NN)                 { idx_off = pos; }
    writeout_kernel<<<NN / 8, 256>>>(e, out, q_off, st_off, idx_off);
}